// round 13
// baseline (speedup 1.0000x reference)
#include <cuda_runtime.h>
#include <cuda_fp16.h>
#include <cstdint>

// Problem constants (fixed by the reference)
#define BB   2
#define SS   2048
#define DD   4096
#define NQH  32
#define NKVH 8
#define HD   128

// Scratch (all fp16): projected Q/K head-major, V transposed [b][kh][d][s];
// converted X and W^T.
__device__ __half g_qh[(size_t)BB * NQH  * SS * HD];   // 32 MB
__device__ __half g_kh[(size_t)BB * NKVH * SS * HD];   //  8 MB
__device__ __half g_vt[(size_t)BB * NKVH * HD * SS];   //  8 MB
__device__ __half g_xh[(size_t)BB * SS * DD];          // 32 MB
__device__ __half g_wt[(size_t)(NQH + 2 * NKVH) * HD * DD];  // 48 MB (rows: WqT, WkT, WvT)

// ---------------------------------------------------------------------------
// Helpers
// ---------------------------------------------------------------------------
__device__ __forceinline__ void cp_async16(uint32_t dst, const void* src) {
    asm volatile("cp.async.cg.shared.global [%0], [%1], 16;"
                 :: "r"(dst), "l"(src));
}
#define CP_COMMIT() asm volatile("cp.async.commit_group;" ::: "memory")
__device__ __forceinline__ uint32_t smem_u32(const void* p) {
    uint32_t a;
    asm("{ .reg .u64 t; cvta.to.shared.u64 t, %1; cvt.u32.u64 %0, t; }"
        : "=r"(a) : "l"(p));
    return a;
}
__device__ __forceinline__ uint32_t h2bits(float a, float b) {
    __half2 h = __floats2half2_rn(a, b);
    return *(uint32_t*)&h;
}

// ldmatrix x4: four 8x8 b16 matrices; lanes 0-7 address m0 rows, 8-15 m1, ...
#define LDSM_X4(r0, r1, r2, r3, addr) \
    asm volatile("ldmatrix.sync.aligned.m8n8.x4.shared.b16 {%0,%1,%2,%3}, [%4];" \
                 : "=r"(r0), "=r"(r1), "=r"(r2), "=r"(r3) : "r"(addr))

// mma.sync m16n8k16 fp16->fp32: D += A*B, A row-major, B col-major
__device__ __forceinline__ void mma16(float* d, const uint32_t* a,
                                      uint32_t b0, uint32_t b1) {
    asm volatile("mma.sync.aligned.m16n8k16.row.col.f32.f16.f16.f32 "
                 "{%0,%1,%2,%3}, {%4,%5,%6,%7}, {%8,%9}, {%0,%1,%2,%3};"
                 : "+f"(d[0]), "+f"(d[1]), "+f"(d[2]), "+f"(d[3])
                 : "r"(a[0]), "r"(a[1]), "r"(a[2]), "r"(a[3]),
                   "r"(b0), "r"(b1));
}

// ---------------------------------------------------------------------------
// Prep: convert X to fp16; transpose Wq/Wk/Wv -> W^T fp16 (one fused launch)
// ---------------------------------------------------------------------------
__global__ void convert_xh(const float* __restrict__ in, __half* __restrict__ out) {
    int i = blockIdx.x * blockDim.x + threadIdx.x;   // float4 index
    float4 v = ((const float4*)in)[i];
    ((uint2*)out)[i] = make_uint2(h2bits(v.x, v.y), h2bits(v.z, v.w));
}

__global__ void transpose_all(const float* __restrict__ wq,
                              const float* __restrict__ wk,
                              const float* __restrict__ wv,
                              __half* __restrict__ out)   // stacked [6144][DD]
{
    __shared__ float t[32][33];
    const float* in; int N, orow;
    if (blockIdx.z == 0)      { in = wq; N = 4096; orow = 0;    }
    else if (blockIdx.z == 1) { in = wk; N = 1024; orow = 4096; }
    else                      { in = wv; N = 1024; orow = 5120; }
    if (blockIdx.x * 32 >= N) return;

    int x  = blockIdx.x * 32 + threadIdx.x;   // n
    int y0 = blockIdx.y * 32;                 // k base
    #pragma unroll
    for (int i = threadIdx.y; i < 32; i += 8)
        t[i][threadIdx.x] = in[(size_t)(y0 + i) * N + x];
    __syncthreads();
    int k  = y0 + threadIdx.x;
    int n0 = blockIdx.x * 32;
    #pragma unroll
    for (int i = threadIdx.y; i < 32; i += 8)
        out[(size_t)(orow + n0 + i) * DD + k] = __float2half(t[threadIdx.x][i]);
}

// ---------------------------------------------------------------------------
// Fused QKV GEMM (fp16 HMMA + ldmatrix) — v2: k-tile 64, 3-stage cp.async
// ring. CTA 128x128, 4 warps (2m x 2n), warp tile 64x64. 2 CTAs/SM.
// Rows: 64 halves + 8 pad = 144 B; LDSM banks 36r = 4r mod 32 distinct.
// ---------------------------------------------------------------------------
#define G_ROW_B   144
#define G_ATILE_B (128 * G_ROW_B)            // 18432 B
#define G_STAGE_B (2 * G_ATILE_B)            // 36864 B (A + B)
#define G_NSTAGE  3
#define GEMM_SMEM (G_NSTAGE * G_STAGE_B)     // 110592 B

__global__ void __launch_bounds__(128, 2)
gemm_fused(const __half* __restrict__ Xh, const __half* __restrict__ WT,
           const float* __restrict__ fcos, const float* __restrict__ fsin,
           __half* __restrict__ Qo, __half* __restrict__ Ko,
           __half* __restrict__ VTo)
{
    extern __shared__ char smg[];
    const uint32_t smb = smem_u32(smg);
    const int tid = threadIdx.x, lane = tid & 31, wid = tid >> 5;
    const int wm = wid >> 1, wn = wid & 1;
    const int g = lane >> 2, q2 = lane & 3;
    const int rBase = blockIdx.y * 128;

    const int aRow = ((lane >> 3) & 1) * 8 + (lane & 7);
    const int aCol = (lane >> 4) * 8;
    const int bRow = ((lane >> 4) & 1) * 8 + (lane & 7);
    const int bCol = ((lane >> 3) & 1) * 8;

    int bx = blockIdx.x, brow, localc, mode;
    if (bx < 32)      { brow = bx * 128;               localc = brow;            mode = 0; }
    else if (bx < 40) { brow = 4096 + (bx - 32) * 128; localc = (bx - 32) * 128; mode = 1; }
    else              { brow = 5120 + (bx - 40) * 128; localc = (bx - 40) * 128; mode = 2; }

    float d[4][8][4];
    #pragma unroll
    for (int mt = 0; mt < 4; mt++)
        #pragma unroll
        for (int nt = 0; nt < 8; nt++)
            #pragma unroll
            for (int i = 0; i < 4; i++) d[mt][nt][i] = 0.f;

    // Load one 64-k tile (A 128x64h + B 128x64h) into stage st.
    auto load_tile = [&](int kt, int st) {
        uint32_t sA = smb + st * G_STAGE_B;
        int k0 = kt * 64;
        #pragma unroll
        for (int i = 0; i < 8; i++) {           // A: 1024 granules
            int gi = tid + i * 128;
            int row = gi >> 3, gc = gi & 7;
            cp_async16(sA + row * G_ROW_B + gc * 16,
                       Xh + (size_t)(rBase + row) * DD + k0 + gc * 8);
        }
        #pragma unroll
        for (int i = 0; i < 8; i++) {           // B: 1024 granules
            int gi = tid + i * 128;
            int row = gi >> 3, gc = gi & 7;
            cp_async16(sA + G_ATILE_B + row * G_ROW_B + gc * 16,
                       WT + (size_t)(brow + row) * DD + k0 + gc * 8);
        }
    };

    load_tile(0, 0); CP_COMMIT();
    load_tile(1, 1); CP_COMMIT();

    const int NT = DD / 64;   // 64 k-tiles
    int stC = 0, stL = 2;     // compute stage, load stage (wrapping mod 3)
    for (int c = 0; c < NT; c++) {
        asm volatile("cp.async.wait_group 1;" ::: "memory");  // tile c ready
        __syncthreads();
        if (c + 2 < NT) load_tile(c + 2, stL);
        CP_COMMIT();
        if (++stL == G_NSTAGE) stL = 0;

        const uint32_t stg = smb + stC * G_STAGE_B;
        if (++stC == G_NSTAGE) stC = 0;
        const uint32_t aBase = stg + (wm * 64 + aRow) * G_ROW_B + aCol * 2;
        const uint32_t bBase = stg + G_ATILE_B + (wn * 64 + bRow) * G_ROW_B + bCol * 2;
        #pragma unroll
        for (int ks = 0; ks < 4; ks++) {
            uint32_t a[4][4];
            #pragma unroll
            for (int mt = 0; mt < 4; mt++)
                LDSM_X4(a[mt][0], a[mt][1], a[mt][2], a[mt][3],
                        aBase + mt * (16 * G_ROW_B) + ks * 32);
            #pragma unroll
            for (int ntp = 0; ntp < 4; ntp++) {
                uint32_t b00, b01, b10, b11;
                LDSM_X4(b00, b01, b10, b11,
                        bBase + ntp * (16 * G_ROW_B) + ks * 32);
                #pragma unroll
                for (int mt = 0; mt < 4; mt++) {
                    mma16(d[mt][2 * ntp],     a[mt], b00, b01);
                    mma16(d[mt][2 * ntp + 1], a[mt], b10, b11);
                }
            }
        }
    }

    // Epilogue: RoPE for Q/K, prescale Q, fp16 stores (V transposed)
    const float scale = 0.08838834764831845f;
    #pragma unroll
    for (int mt = 0; mt < 4; mt++) {
        int row0 = rBase + wm * 64 + mt * 16 + g;
        #pragma unroll
        for (int nt = 0; nt < 8; nt++) {
            int cg = localc + wn * 64 + nt * 8 + 2 * q2;
            int h  = cg >> 7, d0 = cg & 127;
            #pragma unroll
            for (int hf = 0; hf < 2; hf++) {
                int   t = row0 + hf * 8;
                int   b = t >> 11, s = t & 2047;
                float vr = d[mt][nt][hf * 2 + 0];
                float vi = d[mt][nt][hf * 2 + 1];
                if (mode <= 1) {
                    float fc = fcos[s * 64 + (d0 >> 1)];
                    float fs = fsin[s * 64 + (d0 >> 1)];
                    float nr = vr * fc - vi * fs;
                    float ni = vr * fs + vi * fc;
                    vr = nr; vi = ni;
                }
                if (mode == 0) {
                    __half2 h2 = __floats2half2_rn(vr * scale, vi * scale);
                    *(__half2*)(Qo + (((size_t)b * NQH + h) * SS + s) * HD + d0) = h2;
                } else if (mode == 1) {
                    __half2 h2 = __floats2half2_rn(vr, vi);
                    *(__half2*)(Ko + (((size_t)b * NKVH + h) * SS + s) * HD + d0) = h2;
                } else {
                    VTo[(((size_t)b * NKVH + h) * HD + d0)     * SS + s] = __float2half(vr);
                    VTo[(((size_t)b * NKVH + h) * HD + d0 + 1) * SS + s] = __float2half(vi);
                }
            }
        }
    }
}

// ---------------------------------------------------------------------------
// Flash attention (fp16 HMMA + ldmatrix, double-buffered cp.async K/V).
// CTA = 64 q-rows x one (b,h); 4 warps. 2 CTAs/SM. (unchanged)
// ---------------------------------------------------------------------------
#define KV_K_B   (64 * 136 * 2)                 // 17408 B per stage (K)
#define KV_ST_B  (KV_K_B + 128 * 72 * 2)        // 35840 B per stage (K+V)
#define ATTN_SMEM (2 * KV_ST_B)                 // 71680 B

__global__ void __launch_bounds__(128, 2)
attn_mma(const __half* __restrict__ Q, const __half* __restrict__ K,
         const __half* __restrict__ VT, float* __restrict__ out)
{
    extern __shared__ char sma[];
    const uint32_t smB = smem_u32(sma);

    const int tid = threadIdx.x, lane = tid & 31, w = tid >> 5;
    const int g = lane >> 2, q2 = lane & 3;
    const int qBase = blockIdx.x * 64;
    const int bh = blockIdx.y, b = bh >> 5, h = bh & 31, kh = h >> 2;

    const int bRow = ((lane >> 4) & 1) * 8 + (lane & 7);
    const int bCol = ((lane >> 3) & 1) * 8;

    const __half* Qg  = Q  + (((size_t)b * NQH + h) * SS + qBase) * HD;
    const __half* Kg  = K  + ((size_t)b * NKVH + kh) * SS * HD;
    const __half* VTg = VT + ((size_t)b * NKVH + kh) * HD * SS;

    // --- Stage Q into stage-0 K region, extract frags, release
    {
        __half* KPh = (__half*)sma;
        #pragma unroll
        for (int i = 0; i < 8; i++) {
            int c = tid + i * 128;
            int r = c >> 4, q = c & 15;
            *(uint4*)(KPh + r * 136 + q * 8) =
                *(const uint4*)(Qg + (size_t)r * HD + q * 8);
        }
    }
    __syncthreads();

    uint32_t Qf[8][4];
    {
        const int aRow = ((lane >> 3) & 1) * 8 + (lane & 7);
        const int aCol = (lane >> 4) * 8;
        const uint32_t qBaseA = smB + (w * 16 + aRow) * 272 + aCol * 2;
        #pragma unroll
        for (int ks = 0; ks < 8; ks++)
            LDSM_X4(Qf[ks][0], Qf[ks][1], Qf[ks][2], Qf[ks][3],
                    qBaseA + ks * 32);
    }
    __syncthreads();   // Q reads done; stage 0 free for K

    auto load_kv = [&](int kt, int st) {
        const uint32_t sK = smB + st * KV_ST_B;
        const uint32_t sV = sK + KV_K_B;
        #pragma unroll
        for (int i = 0; i < 8; i++) {
            int c = tid + i * 128;
            int r = c >> 4, q = c & 15;
            cp_async16(sK + r * 272 + q * 16,
                       Kg + (size_t)(kt * 64 + r) * HD + q * 8);
        }
        #pragma unroll
        for (int i = 0; i < 8; i++) {
            int c = tid + i * 128;
            int dd = c >> 3, q = c & 7;
            cp_async16(sV + dd * 144 + q * 16,
                       VTg + (size_t)dd * SS + kt * 64 + q * 8);
        }
    };

    load_kv(0, 0); CP_COMMIT();
    load_kv(1, 1); CP_COMMIT();

    float m0 = -1e30f, m1 = -1e30f, l0 = 0.f, l1 = 0.f;
    float o[16][4];
    #pragma unroll
    for (int dt = 0; dt < 16; dt++)
        #pragma unroll
        for (int i = 0; i < 4; i++) o[dt][i] = 0.f;

    for (int kt = 0; kt < SS / 64; kt++) {
        const int st = kt & 1;
        const uint32_t stg = smB + st * KV_ST_B;
        const uint32_t kBaseB = stg + bRow * 272 + bCol * 2;
        const uint32_t vBaseB = stg + KV_K_B + bRow * 144 + bCol * 2;
        uint32_t* Pw = (uint32_t*)(sma + st * KV_ST_B) + w * (16 * 36);

        asm volatile("cp.async.wait_group 1;" ::: "memory");  // tile kt ready
        __syncthreads();

        float s[8][4];
        #pragma unroll
        for (int nt = 0; nt < 8; nt++)
            #pragma unroll
            for (int i = 0; i < 4; i++) s[nt][i] = 0.f;

        #pragma unroll
        for (int ks = 0; ks < 8; ks++) {
            #pragma unroll
            for (int ntp = 0; ntp < 4; ntp++) {
                uint32_t b00, b01, b10, b11;
                LDSM_X4(b00, b01, b10, b11,
                        kBaseB + ntp * (16 * 272) + ks * 32);
                mma16(s[2 * ntp],     Qf[ks], b00, b01);
                mma16(s[2 * ntp + 1], Qf[ks], b10, b11);
            }
        }

        float mx0 = -1e30f, mx1 = -1e30f;
        #pragma unroll
        for (int nt = 0; nt < 8; nt++) {
            mx0 = fmaxf(mx0, fmaxf(s[nt][0], s[nt][1]));
            mx1 = fmaxf(mx1, fmaxf(s[nt][2], s[nt][3]));
        }
        mx0 = fmaxf(mx0, __shfl_xor_sync(0xffffffffu, mx0, 1));
        mx0 = fmaxf(mx0, __shfl_xor_sync(0xffffffffu, mx0, 2));
        mx1 = fmaxf(mx1, __shfl_xor_sync(0xffffffffu, mx1, 1));
        mx1 = fmaxf(mx1, __shfl_xor_sync(0xffffffffu, mx1, 2));
        float mn0 = fmaxf(m0, mx0), mn1 = fmaxf(m1, mx1);
        float corr0 = __expf(m0 - mn0), corr1 = __expf(m1 - mn1);
        m0 = mn0; m1 = mn1;

        float p0[8][2], p1[8][2], sum0 = 0.f, sum1 = 0.f;
        #pragma unroll
        for (int nt = 0; nt < 8; nt++) {
            p0[nt][0] = __expf(s[nt][0] - mn0);
            p0[nt][1] = __expf(s[nt][1] - mn0);
            p1[nt][0] = __expf(s[nt][2] - mn1);
            p1[nt][1] = __expf(s[nt][3] - mn1);
            sum0 += p0[nt][0] + p0[nt][1];
            sum1 += p1[nt][0] + p1[nt][1];
        }

        __syncthreads();   // ALL warps done reading K before P overlays it

        #pragma unroll
        for (int nt = 0; nt < 8; nt++) {
            int pw = nt * 4 + q2;
            Pw[g * 36 + pw]       = h2bits(p0[nt][0], p0[nt][1]);
            Pw[(g + 8) * 36 + pw] = h2bits(p1[nt][0], p1[nt][1]);
        }
        sum0 += __shfl_xor_sync(0xffffffffu, sum0, 1);
        sum0 += __shfl_xor_sync(0xffffffffu, sum0, 2);
        sum1 += __shfl_xor_sync(0xffffffffu, sum1, 1);
        sum1 += __shfl_xor_sync(0xffffffffu, sum1, 2);
        l0 = l0 * corr0 + sum0;
        l1 = l1 * corr1 + sum1;
        #pragma unroll
        for (int dt = 0; dt < 16; dt++) {
            o[dt][0] *= corr0; o[dt][1] *= corr0;
            o[dt][2] *= corr1; o[dt][3] *= corr1;
        }
        __syncwarp();   // own warp's P visible before A-frag reads

        #pragma unroll
        for (int ks = 0; ks < 4; ks++) {
            const int col = ks * 8 + q2;
            uint32_t a[4];
            a[0] = Pw[g * 36 + col];
            a[1] = Pw[(g + 8) * 36 + col];
            a[2] = Pw[g * 36 + col + 4];
            a[3] = Pw[(g + 8) * 36 + col + 4];
            #pragma unroll
            for (int dtp = 0; dtp < 8; dtp++) {
                uint32_t b00, b01, b10, b11;
                LDSM_X4(b00, b01, b10, b11,
                        vBaseB + dtp * (16 * 144) + ks * 32);
                mma16(o[2 * dtp],     a, b00, b01);
                mma16(o[2 * dtp + 1], a, b10, b11);
            }
        }
        __syncthreads();   // stage fully dead (P + V consumed)

        if (kt + 2 < SS / 64) load_kv(kt + 2, st);
        CP_COMMIT();       // always commit — uniform group accounting
    }

    // Epilogue
    float inv0 = 1.f / l0, inv1 = 1.f / l1;
    int r0 = qBase + w * 16 + g;
    #pragma unroll
    for (int dt = 0; dt < 16; dt++) {
        int d0 = dt * 8 + 2 * q2;
        *(float2*)(out + ((size_t)b * SS + r0) * DD + h * HD + d0)
            = make_float2(o[dt][0] * inv0, o[dt][1] * inv0);
        *(float2*)(out + ((size_t)b * SS + r0 + 8) * DD + h * HD + d0)
            = make_float2(o[dt][2] * inv1, o[dt][3] * inv1);
    }
}

// ---------------------------------------------------------------------------
// Launch
// ---------------------------------------------------------------------------
extern "C" void kernel_launch(void* const* d_in, const int* in_sizes, int n_in,
                              void* d_out, int out_size)
{
    const float* x    = (const float*)d_in[0];
    const float* wq   = (const float*)d_in[1];
    const float* wk   = (const float*)d_in[2];
    const float* wv   = (const float*)d_in[3];
    const float* fcos = (const float*)d_in[6];
    const float* fsin = (const float*)d_in[7];
    float*       out  = (float*)d_out;

    __half *qh, *kh, *vt, *xh, *wt;
    cudaGetSymbolAddress((void**)&qh, g_qh);
    cudaGetSymbolAddress((void**)&kh, g_kh);
    cudaGetSymbolAddress((void**)&vt, g_vt);
    cudaGetSymbolAddress((void**)&xh, g_xh);
    cudaGetSymbolAddress((void**)&wt, g_wt);

    cudaFuncSetAttribute(gemm_fused,
                         cudaFuncAttributeMaxDynamicSharedMemorySize, GEMM_SMEM);
    cudaFuncSetAttribute(attn_mma,
                         cudaFuncAttributeMaxDynamicSharedMemorySize, ATTN_SMEM);

    // Prep: X -> fp16; W -> W^T fp16 (one fused transpose launch)
    convert_xh<<<(BB * SS * DD / 4) / 256, 256>>>(x, xh);
    transpose_all<<<dim3(128, DD / 32, 3), dim3(32, 8)>>>(wq, wk, wv, wt);

    // Fused QKV projections: 48 col-tiles x 32 row-tiles
    gemm_fused<<<dim3(48, 32), 128, GEMM_SMEM>>>(xh, wt, fcos, fsin, qh, kh, vt);

    // Attention: 32 q-tiles x (B*H = 64)
    attn_mma<<<dim3(32, 64), 128, ATTN_SMEM>>>(qh, kh, vt, out);
}

// round 15
// speedup vs baseline: 1.0864x; 1.0864x over previous
#include <cuda_runtime.h>
#include <cuda_fp16.h>
#include <cstdint>

// Problem constants (fixed by the reference)
#define BB   2
#define SS   2048
#define DD   4096
#define NQH  32
#define NKVH 8
#define HD   128

// Scratch (all fp16): projected Q/K head-major, V transposed [b][kh][d][s];
// converted X and W^T.
__device__ __half g_qh[(size_t)BB * NQH  * SS * HD];   // 32 MB
__device__ __half g_kh[(size_t)BB * NKVH * SS * HD];   //  8 MB
__device__ __half g_vt[(size_t)BB * NKVH * HD * SS];   //  8 MB
__device__ __half g_xh[(size_t)BB * SS * DD];          // 32 MB
__device__ __half g_wt[(size_t)(NQH + 2 * NKVH) * HD * DD];  // 48 MB (rows: WqT, WkT, WvT)

// ---------------------------------------------------------------------------
// Helpers
// ---------------------------------------------------------------------------
__device__ __forceinline__ void cp_async16(uint32_t dst, const void* src) {
    asm volatile("cp.async.cg.shared.global [%0], [%1], 16;"
                 :: "r"(dst), "l"(src));
}
#define CP_COMMIT() asm volatile("cp.async.commit_group;" ::: "memory")
__device__ __forceinline__ uint32_t smem_u32(const void* p) {
    uint32_t a;
    asm("{ .reg .u64 t; cvta.to.shared.u64 t, %1; cvt.u32.u64 %0, t; }"
        : "=r"(a) : "l"(p));
    return a;
}
__device__ __forceinline__ uint32_t h2bits(float a, float b) {
    __half2 h = __floats2half2_rn(a, b);
    return *(uint32_t*)&h;
}

// ldmatrix x4: four 8x8 b16 matrices; lanes 0-7 address m0 rows, 8-15 m1, ...
#define LDSM_X4(r0, r1, r2, r3, addr) \
    asm volatile("ldmatrix.sync.aligned.m8n8.x4.shared.b16 {%0,%1,%2,%3}, [%4];" \
                 : "=r"(r0), "=r"(r1), "=r"(r2), "=r"(r3) : "r"(addr))

// mma.sync m16n8k16 fp16->fp32: D += A*B, A row-major, B col-major
__device__ __forceinline__ void mma16(float* d, const uint32_t* a,
                                      uint32_t b0, uint32_t b1) {
    asm volatile("mma.sync.aligned.m16n8k16.row.col.f32.f16.f16.f32 "
                 "{%0,%1,%2,%3}, {%4,%5,%6,%7}, {%8,%9}, {%0,%1,%2,%3};"
                 : "+f"(d[0]), "+f"(d[1]), "+f"(d[2]), "+f"(d[3])
                 : "r"(a[0]), "r"(a[1]), "r"(a[2]), "r"(a[3]),
                   "r"(b0), "r"(b1));
}

// ---------------------------------------------------------------------------
// Prep: convert X to fp16; transpose Wq/Wk/Wv -> W^T fp16 (one fused launch)
// ---------------------------------------------------------------------------
__global__ void convert_xh(const float* __restrict__ in, __half* __restrict__ out) {
    int i = blockIdx.x * blockDim.x + threadIdx.x;   // float4 index
    float4 v = ((const float4*)in)[i];
    ((uint2*)out)[i] = make_uint2(h2bits(v.x, v.y), h2bits(v.z, v.w));
}

__global__ void transpose_all(const float* __restrict__ wq,
                              const float* __restrict__ wk,
                              const float* __restrict__ wv,
                              __half* __restrict__ out)   // stacked [6144][DD]
{
    __shared__ float t[32][33];
    const float* in; int N, orow;
    if (blockIdx.z == 0)      { in = wq; N = 4096; orow = 0;    }
    else if (blockIdx.z == 1) { in = wk; N = 1024; orow = 4096; }
    else                      { in = wv; N = 1024; orow = 5120; }
    if (blockIdx.x * 32 >= N) return;

    int x  = blockIdx.x * 32 + threadIdx.x;   // n
    int y0 = blockIdx.y * 32;                 // k base
    #pragma unroll
    for (int i = threadIdx.y; i < 32; i += 8)
        t[i][threadIdx.x] = in[(size_t)(y0 + i) * N + x];
    __syncthreads();
    int k  = y0 + threadIdx.x;
    int n0 = blockIdx.x * 32;
    #pragma unroll
    for (int i = threadIdx.y; i < 32; i += 8)
        out[(size_t)(orow + n0 + i) * DD + k] = __float2half(t[threadIdx.x][i]);
}

// ---------------------------------------------------------------------------
// Fused QKV GEMM (fp16 HMMA + ldmatrix): CTA 128x128, k-tile 32, 4 warps
// (2m x 2n), warp tile 64x64. 4-stage cp.async pipeline. 2 CTAs/SM.
// (REVERTED to the proven R12 configuration)
// ---------------------------------------------------------------------------
#define ATILE_B (128 * 80)          // 10240 B
#define STAGE_B (2 * ATILE_B)       // 20480 B
#define G_NSTAGE 4
#define GEMM_SMEM (G_NSTAGE * STAGE_B)   // 81920 B

__global__ void __launch_bounds__(128, 2)
gemm_fused(const __half* __restrict__ Xh, const __half* __restrict__ WT,
           const float* __restrict__ fcos, const float* __restrict__ fsin,
           __half* __restrict__ Qo, __half* __restrict__ Ko,
           __half* __restrict__ VTo)
{
    extern __shared__ char smg[];
    const uint32_t smb = smem_u32(smg);
    const int tid = threadIdx.x, lane = tid & 31, wid = tid >> 5;
    const int wm = wid >> 1, wn = wid & 1;
    const int g = lane >> 2, q2 = lane & 3;
    const int rBase = blockIdx.y * 128;

    const int aRow = ((lane >> 3) & 1) * 8 + (lane & 7);
    const int aCol = (lane >> 4) * 8;
    const int bRow = ((lane >> 4) & 1) * 8 + (lane & 7);
    const int bCol = ((lane >> 3) & 1) * 8;

    int bx = blockIdx.x, brow, localc, mode;
    if (bx < 32)      { brow = bx * 128;               localc = brow;            mode = 0; }
    else if (bx < 40) { brow = 4096 + (bx - 32) * 128; localc = (bx - 32) * 128; mode = 1; }
    else              { brow = 5120 + (bx - 40) * 128; localc = (bx - 40) * 128; mode = 2; }

    float d[4][8][4];
    #pragma unroll
    for (int mt = 0; mt < 4; mt++)
        #pragma unroll
        for (int nt = 0; nt < 8; nt++)
            #pragma unroll
            for (int i = 0; i < 4; i++) d[mt][nt][i] = 0.f;

    auto load_tile = [&](int kt, int st) {
        uint32_t sA = smb + st * STAGE_B;
        int k0 = kt * 32;
        #pragma unroll
        for (int i = 0; i < 4; i++) {
            int gi = tid + i * 128;
            int row = gi >> 2, gc = gi & 3;
            cp_async16(sA + row * 80 + gc * 16,
                       Xh + (size_t)(rBase + row) * DD + k0 + gc * 8);
        }
        #pragma unroll
        for (int i = 0; i < 4; i++) {
            int gi = tid + i * 128;
            int row = gi >> 2, gc = gi & 3;
            cp_async16(sA + ATILE_B + row * 80 + gc * 16,
                       WT + (size_t)(brow + row) * DD + k0 + gc * 8);
        }
    };

    #pragma unroll
    for (int t = 0; t < G_NSTAGE - 1; t++) { load_tile(t, t); CP_COMMIT(); }

    const int NT = DD / 32;   // 128 k-tiles
    for (int c = 0; c < NT; c++) {
        asm volatile("cp.async.wait_group 2;" ::: "memory");
        __syncthreads();
        if (c + 3 < NT) load_tile(c + 3, (c + 3) & 3);
        CP_COMMIT();

        const uint32_t stg = smb + (c & 3) * STAGE_B;
        const uint32_t aBase = stg + (wm * 64 + aRow) * 80 + aCol * 2;
        const uint32_t bBase = stg + ATILE_B + (wn * 64 + bRow) * 80 + bCol * 2;
        #pragma unroll
        for (int ks = 0; ks < 2; ks++) {
            uint32_t a[4][4];
            #pragma unroll
            for (int mt = 0; mt < 4; mt++)
                LDSM_X4(a[mt][0], a[mt][1], a[mt][2], a[mt][3],
                        aBase + mt * (16 * 80) + ks * 32);
            #pragma unroll
            for (int ntp = 0; ntp < 4; ntp++) {
                uint32_t b00, b01, b10, b11;
                LDSM_X4(b00, b01, b10, b11,
                        bBase + ntp * (16 * 80) + ks * 32);
                #pragma unroll
                for (int mt = 0; mt < 4; mt++) {
                    mma16(d[mt][2 * ntp],     a[mt], b00, b01);
                    mma16(d[mt][2 * ntp + 1], a[mt], b10, b11);
                }
            }
        }
    }

    // Epilogue: RoPE for Q/K, prescale Q, fp16 stores (V transposed)
    const float scale = 0.08838834764831845f;
    #pragma unroll
    for (int mt = 0; mt < 4; mt++) {
        int row0 = rBase + wm * 64 + mt * 16 + g;
        #pragma unroll
        for (int nt = 0; nt < 8; nt++) {
            int cg = localc + wn * 64 + nt * 8 + 2 * q2;
            int h  = cg >> 7, d0 = cg & 127;
            #pragma unroll
            for (int hf = 0; hf < 2; hf++) {
                int   t = row0 + hf * 8;
                int   b = t >> 11, s = t & 2047;
                float vr = d[mt][nt][hf * 2 + 0];
                float vi = d[mt][nt][hf * 2 + 1];
                if (mode <= 1) {
                    float fc = fcos[s * 64 + (d0 >> 1)];
                    float fs = fsin[s * 64 + (d0 >> 1)];
                    float nr = vr * fc - vi * fs;
                    float ni = vr * fs + vi * fc;
                    vr = nr; vi = ni;
                }
                if (mode == 0) {
                    __half2 h2 = __floats2half2_rn(vr * scale, vi * scale);
                    *(__half2*)(Qo + (((size_t)b * NQH + h) * SS + s) * HD + d0) = h2;
                } else if (mode == 1) {
                    __half2 h2 = __floats2half2_rn(vr, vi);
                    *(__half2*)(Ko + (((size_t)b * NKVH + h) * SS + s) * HD + d0) = h2;
                } else {
                    VTo[(((size_t)b * NKVH + h) * HD + d0)     * SS + s] = __float2half(vr);
                    VTo[(((size_t)b * NKVH + h) * HD + d0 + 1) * SS + s] = __float2half(vi);
                }
            }
        }
    }
}

// ---------------------------------------------------------------------------
// Flash attention (fp16 HMMA + ldmatrix, double-buffered cp.async K/V) — v4:
// P kept entirely in registers (D-frag of S == A-frag of P for m16n8k16).
// No P smem round-trip, no K-overlay barrier: 2 syncthreads/tile.
// CTA = 64 q-rows x one (b,h); 4 warps. 2 CTAs/SM.
// ---------------------------------------------------------------------------
#define KV_K_B   (64 * 136 * 2)                 // 17408 B per stage (K)
#define KV_ST_B  (KV_K_B + 128 * 72 * 2)        // 35840 B per stage (K+V)
#define ATTN_SMEM (2 * KV_ST_B)                 // 71680 B

__global__ void __launch_bounds__(128, 2)
attn_mma(const __half* __restrict__ Q, const __half* __restrict__ K,
         const __half* __restrict__ VT, float* __restrict__ out)
{
    extern __shared__ char sma[];
    const uint32_t smB = smem_u32(sma);

    const int tid = threadIdx.x, lane = tid & 31, w = tid >> 5;
    const int g = lane >> 2, q2 = lane & 3;
    const int qBase = blockIdx.x * 64;
    const int bh = blockIdx.y, b = bh >> 5, h = bh & 31, kh = h >> 2;

    const int bRow = ((lane >> 4) & 1) * 8 + (lane & 7);
    const int bCol = ((lane >> 3) & 1) * 8;

    const __half* Qg  = Q  + (((size_t)b * NQH + h) * SS + qBase) * HD;
    const __half* Kg  = K  + ((size_t)b * NKVH + kh) * SS * HD;
    const __half* VTg = VT + ((size_t)b * NKVH + kh) * HD * SS;

    // --- Stage Q into stage-0 K region, extract frags, release
    {
        __half* KPh = (__half*)sma;
        #pragma unroll
        for (int i = 0; i < 8; i++) {
            int c = tid + i * 128;
            int r = c >> 4, q = c & 15;
            *(uint4*)(KPh + r * 136 + q * 8) =
                *(const uint4*)(Qg + (size_t)r * HD + q * 8);
        }
    }
    __syncthreads();

    uint32_t Qf[8][4];
    {
        const int aRow = ((lane >> 3) & 1) * 8 + (lane & 7);
        const int aCol = (lane >> 4) * 8;
        const uint32_t qBaseA = smB + (w * 16 + aRow) * 272 + aCol * 2;
        #pragma unroll
        for (int ks = 0; ks < 8; ks++)
            LDSM_X4(Qf[ks][0], Qf[ks][1], Qf[ks][2], Qf[ks][3],
                    qBaseA + ks * 32);
    }
    __syncthreads();   // Q reads done; stage 0 free for K

    auto load_kv = [&](int kt, int st) {
        const uint32_t sK = smB + st * KV_ST_B;
        const uint32_t sV = sK + KV_K_B;
        #pragma unroll
        for (int i = 0; i < 8; i++) {
            int c = tid + i * 128;
            int r = c >> 4, q = c & 15;
            cp_async16(sK + r * 272 + q * 16,
                       Kg + (size_t)(kt * 64 + r) * HD + q * 8);
        }
        #pragma unroll
        for (int i = 0; i < 8; i++) {
            int c = tid + i * 128;
            int dd = c >> 3, q = c & 7;
            cp_async16(sV + dd * 144 + q * 16,
                       VTg + (size_t)dd * SS + kt * 64 + q * 8);
        }
    };

    load_kv(0, 0); CP_COMMIT();
    load_kv(1, 1); CP_COMMIT();

    float m0 = -1e30f, m1 = -1e30f, l0 = 0.f, l1 = 0.f;
    float o[16][4];
    #pragma unroll
    for (int dt = 0; dt < 16; dt++)
        #pragma unroll
        for (int i = 0; i < 4; i++) o[dt][i] = 0.f;

    for (int kt = 0; kt < SS / 64; kt++) {
        const int st = kt & 1;
        const uint32_t stg = smB + st * KV_ST_B;
        const uint32_t kBaseB = stg + bRow * 272 + bCol * 2;
        const uint32_t vBaseB = stg + KV_K_B + bRow * 144 + bCol * 2;

        asm volatile("cp.async.wait_group 1;" ::: "memory");  // tile kt ready
        __syncthreads();

        // S = Q K^T : m16 x n64, k=128 (8 k16 steps)
        float s[8][4];
        #pragma unroll
        for (int nt = 0; nt < 8; nt++)
            #pragma unroll
            for (int i = 0; i < 4; i++) s[nt][i] = 0.f;

        #pragma unroll
        for (int ks = 0; ks < 8; ks++) {
            #pragma unroll
            for (int ntp = 0; ntp < 4; ntp++) {
                uint32_t b00, b01, b10, b11;
                LDSM_X4(b00, b01, b10, b11,
                        kBaseB + ntp * (16 * 272) + ks * 32);
                mma16(s[2 * ntp],     Qf[ks], b00, b01);
                mma16(s[2 * ntp + 1], Qf[ks], b10, b11);
            }
        }

        // Online softmax; P packed straight into A-fragment registers
        float mx0 = -1e30f, mx1 = -1e30f;
        #pragma unroll
        for (int nt = 0; nt < 8; nt++) {
            mx0 = fmaxf(mx0, fmaxf(s[nt][0], s[nt][1]));
            mx1 = fmaxf(mx1, fmaxf(s[nt][2], s[nt][3]));
        }
        mx0 = fmaxf(mx0, __shfl_xor_sync(0xffffffffu, mx0, 1));
        mx0 = fmaxf(mx0, __shfl_xor_sync(0xffffffffu, mx0, 2));
        mx1 = fmaxf(mx1, __shfl_xor_sync(0xffffffffu, mx1, 1));
        mx1 = fmaxf(mx1, __shfl_xor_sync(0xffffffffu, mx1, 2));
        float mn0 = fmaxf(m0, mx0), mn1 = fmaxf(m1, mx1);
        float corr0 = __expf(m0 - mn0), corr1 = __expf(m1 - mn1);
        m0 = mn0; m1 = mn1;

        uint32_t pA0[8], pA1[8];   // pA0[nt]: rows g; pA1[nt]: rows g+8
        float sum0 = 0.f, sum1 = 0.f;
        #pragma unroll
        for (int nt = 0; nt < 8; nt++) {
            float p00 = __expf(s[nt][0] - mn0);
            float p01 = __expf(s[nt][1] - mn0);
            float p10 = __expf(s[nt][2] - mn1);
            float p11 = __expf(s[nt][3] - mn1);
            sum0 += p00 + p01; sum1 += p10 + p11;
            pA0[nt] = h2bits(p00, p01);
            pA1[nt] = h2bits(p10, p11);
        }
        sum0 += __shfl_xor_sync(0xffffffffu, sum0, 1);
        sum0 += __shfl_xor_sync(0xffffffffu, sum0, 2);
        sum1 += __shfl_xor_sync(0xffffffffu, sum1, 1);
        sum1 += __shfl_xor_sync(0xffffffffu, sum1, 2);
        l0 = l0 * corr0 + sum0;
        l1 = l1 * corr1 + sum1;
        #pragma unroll
        for (int dt = 0; dt < 16; dt++) {
            o[dt][0] *= corr0; o[dt][1] *= corr0;
            o[dt][2] *= corr1; o[dt][3] *= corr1;
        }

        // O += P V : k=64 keys (4 k16 steps); A direct from registers
        #pragma unroll
        for (int ks = 0; ks < 4; ks++) {
            uint32_t a[4];
            a[0] = pA0[2 * ks];
            a[1] = pA1[2 * ks];
            a[2] = pA0[2 * ks + 1];
            a[3] = pA1[2 * ks + 1];
            #pragma unroll
            for (int dtp = 0; dtp < 8; dtp++) {
                uint32_t b00, b01, b10, b11;
                LDSM_X4(b00, b01, b10, b11,
                        vBaseB + dtp * (16 * 144) + ks * 32);
                mma16(o[2 * dtp],     a, b00, b01);
                mma16(o[2 * dtp + 1], a, b10, b11);
            }
        }
        __syncthreads();   // stage fully dead (K + V consumed) before refill

        if (kt + 2 < SS / 64) load_kv(kt + 2, st);
        CP_COMMIT();       // always commit — uniform group accounting
    }

    // Epilogue
    float inv0 = 1.f / l0, inv1 = 1.f / l1;
    int r0 = qBase + w * 16 + g;
    #pragma unroll
    for (int dt = 0; dt < 16; dt++) {
        int d0 = dt * 8 + 2 * q2;
        *(float2*)(out + ((size_t)b * SS + r0) * DD + h * HD + d0)
            = make_float2(o[dt][0] * inv0, o[dt][1] * inv0);
        *(float2*)(out + ((size_t)b * SS + r0 + 8) * DD + h * HD + d0)
            = make_float2(o[dt][2] * inv1, o[dt][3] * inv1);
    }
}

// ---------------------------------------------------------------------------
// Launch
// ---------------------------------------------------------------------------
extern "C" void kernel_launch(void* const* d_in, const int* in_sizes, int n_in,
                              void* d_out, int out_size)
{
    const float* x    = (const float*)d_in[0];
    const float* wq   = (const float*)d_in[1];
    const float* wk   = (const float*)d_in[2];
    const float* wv   = (const float*)d_in[3];
    const float* fcos = (const float*)d_in[6];
    const float* fsin = (const float*)d_in[7];
    float*       out  = (float*)d_out;

    __half *qh, *kh, *vt, *xh, *wt;
    cudaGetSymbolAddress((void**)&qh, g_qh);
    cudaGetSymbolAddress((void**)&kh, g_kh);
    cudaGetSymbolAddress((void**)&vt, g_vt);
    cudaGetSymbolAddress((void**)&xh, g_xh);
    cudaGetSymbolAddress((void**)&wt, g_wt);

    cudaFuncSetAttribute(gemm_fused,
                         cudaFuncAttributeMaxDynamicSharedMemorySize, GEMM_SMEM);
    cudaFuncSetAttribute(attn_mma,
                         cudaFuncAttributeMaxDynamicSharedMemorySize, ATTN_SMEM);

    // Prep: X -> fp16; W -> W^T fp16 (one fused transpose launch)
    convert_xh<<<(BB * SS * DD / 4) / 256, 256>>>(x, xh);
    transpose_all<<<dim3(128, DD / 32, 3), dim3(32, 8)>>>(wq, wk, wv, wt);

    // Fused QKV projections: 48 col-tiles x 32 row-tiles
    gemm_fused<<<dim3(48, 32), 128, GEMM_SMEM>>>(xh, wt, fcos, fsin, qh, kh, vt);

    // Attention: 32 q-tiles x (B*H = 64)
    attn_mma<<<dim3(32, 64), 128, ATTN_SMEM>>>(qh, kh, vt, out);
}